// round 1
// baseline (speedup 1.0000x reference)
#include <cuda_runtime.h>

#define D        64
#define KCODES   1024
#define TK       128      // codes per smem tile (128*64*4 = 32 KB)
#define BLOCK    256

// Scratch (allocation-free rule: __device__ globals)
__device__ float g_esq[KCODES];
__device__ float g_partials[1024];

// ---------------------------------------------------------------------------
// packed f32x2 helpers (FFMA2 path — only reachable via PTX, not from C++)
// ---------------------------------------------------------------------------
__device__ __forceinline__ void ffma2(unsigned long long& d,
                                      unsigned long long a,
                                      unsigned long long b) {
    asm("fma.rn.f32x2 %0, %1, %2, %0;" : "+l"(d) : "l"(a), "l"(b));
}
__device__ __forceinline__ void fadd2(unsigned long long& d,
                                      unsigned long long a) {
    asm("add.rn.f32x2 %0, %0, %1;" : "+l"(d) : "l"(a));
}

// ---------------------------------------------------------------------------
// Kernel 0: |e_k|^2 for every code
// ---------------------------------------------------------------------------
__global__ void esq_kernel(const float* __restrict__ emb) {
    int k = blockIdx.x * blockDim.x + threadIdx.x;
    if (k < KCODES) {
        const float4* e = (const float4*)(emb + (size_t)k * D);
        float s = 0.f;
#pragma unroll
        for (int i = 0; i < D / 4; i++) {
            float4 v = e[i];
            s += v.x * v.x + v.y * v.y + v.z * v.z + v.w * v.w;
        }
        g_esq[k] = s;
    }
}

// ---------------------------------------------------------------------------
// Kernel 1: per-row argmin over K codes + quant gather + indices + partial loss
// ---------------------------------------------------------------------------
__global__ __launch_bounds__(BLOCK, 2) void vq_kernel(
    const float* __restrict__ x, const float* __restrict__ emb,
    float* __restrict__ out, int N)
{
    __shared__ __align__(16) float s_e[TK * D];
    __shared__ float s_esq[TK];
    __shared__ float s_red[BLOCK / 32];

    const int row    = blockIdx.x * BLOCK + threadIdx.x;
    const bool valid = (row < N);

    // ---- load my row as 32 packed f32x2 operands ----
    unsigned long long xp[32];
    float xsq = 0.f;
    if (valid) {
        const ulonglong2* xr = (const ulonglong2*)(x + (size_t)row * D);
#pragma unroll
        for (int i = 0; i < 16; i++) {
            ulonglong2 v = xr[i];
            xp[2 * i]     = v.x;
            xp[2 * i + 1] = v.y;
        }
#pragma unroll
        for (int j = 0; j < 32; j++) {
            float2 f = *(float2*)&xp[j];
            xsq += f.x * f.x + f.y * f.y;
        }
    } else {
#pragma unroll
        for (int j = 0; j < 32; j++) xp[j] = 0ull;
    }

    float best = 3.402823466e38f;
    int   bidx = 0;

    for (int t0 = 0; t0 < KCODES; t0 += TK) {
        __syncthreads();
        // cooperative tile load: TK codes, contiguous 32 KB copy
        {
            const float4* src = (const float4*)(emb + (size_t)t0 * D);
            float4* dst = (float4*)s_e;
            for (int i = threadIdx.x; i < TK * D / 4; i += BLOCK) dst[i] = src[i];
            if (threadIdx.x < TK) s_esq[threadIdx.x] = g_esq[t0 + threadIdx.x];
        }
        __syncthreads();

#pragma unroll 2
        for (int kk = 0; kk < TK; kk++) {
            const ulonglong2* er = (const ulonglong2*)(s_e + kk * D);
            unsigned long long a0 = 0ull, a1 = 0ull, a2 = 0ull, a3 = 0ull;
#pragma unroll
            for (int i = 0; i < 16; i++) {
                ulonglong2 ev = er[i];   // broadcast LDS.128 (uniform addr)
                if (i & 1) { ffma2(a2, xp[2 * i], ev.x); ffma2(a3, xp[2 * i + 1], ev.y); }
                else       { ffma2(a0, xp[2 * i], ev.x); ffma2(a1, xp[2 * i + 1], ev.y); }
            }
            fadd2(a0, a2); fadd2(a1, a3); fadd2(a0, a1);
            float2 dp  = *(float2*)&a0;
            float  dot = dp.x + dp.y;
            // mirror reference: (input_sq + embed_sq) - 2*dot, same rounding/ties
            float dist = (xsq + s_esq[kk]) - 2.0f * dot;
            if (dist < best) { best = dist; bidx = t0 + kk; }
        }
    }

    // ---- epilogue: gather quant, write index, accumulate (q - x)^2 ----
    float errsum = 0.f;
    if (valid) {
        const float4* eb = (const float4*)(emb + (size_t)bidx * D);
        float4* oq = (float4*)(out + (size_t)row * D);
#pragma unroll
        for (int i = 0; i < 16; i++) {
            float4 e = eb[i];
            oq[i] = e;                            // quant_st == embedding[idx]
            float2 a = *(float2*)&xp[2 * i];
            float2 b = *(float2*)&xp[2 * i + 1];
            float d0 = e.x - a.x, d1 = e.y - a.y;
            float d2 = e.z - b.x, d3 = e.w - b.y;
            errsum += d0 * d0 + d1 * d1 + d2 * d2 + d3 * d3;
        }
        out[(size_t)N * D + 1 + row] = (float)bidx;  // encoding index as f32
    }

    // deterministic block reduction of errsum
#pragma unroll
    for (int o = 16; o; o >>= 1) errsum += __shfl_down_sync(0xffffffffu, errsum, o);
    if ((threadIdx.x & 31) == 0) s_red[threadIdx.x >> 5] = errsum;
    __syncthreads();
    if (threadIdx.x < 32) {
        float v = (threadIdx.x < BLOCK / 32) ? s_red[threadIdx.x] : 0.f;
#pragma unroll
        for (int o = 4; o; o >>= 1) v += __shfl_down_sync(0xffffffffu, v, o);
        if (threadIdx.x == 0) g_partials[blockIdx.x] = v;
    }
}

// ---------------------------------------------------------------------------
// Kernel 2: deterministic final loss reduction
// ---------------------------------------------------------------------------
__global__ void loss_kernel(float* __restrict__ out, int nblocks, int N) {
    __shared__ float s_red[16];
    float v = 0.f;
    for (int i = threadIdx.x; i < nblocks; i += blockDim.x) v += g_partials[i];
#pragma unroll
    for (int o = 16; o; o >>= 1) v += __shfl_down_sync(0xffffffffu, v, o);
    if ((threadIdx.x & 31) == 0) s_red[threadIdx.x >> 5] = v;
    __syncthreads();
    if (threadIdx.x < 32) {
        float t = (threadIdx.x < (int)(blockDim.x / 32)) ? s_red[threadIdx.x] : 0.f;
#pragma unroll
        for (int o = 8; o; o >>= 1) t += __shfl_down_sync(0xffffffffu, t, o);
        if (threadIdx.x == 0) {
            // loss = q_latent + 0.25 * e_latent = 1.25 * mean((q - x)^2)
            out[(size_t)N * D] = 1.25f * t / ((float)N * (float)D);
        }
    }
}

// ---------------------------------------------------------------------------
extern "C" void kernel_launch(void* const* d_in, const int* in_sizes, int n_in,
                              void* d_out, int out_size) {
    const float* x   = (const float*)d_in[0];   // inputs  [B,T,D] fp32
    const float* emb = (const float*)d_in[1];   // embedding [K,D] fp32
    float* out = (float*)d_out;                 // [N*D quant | 1 loss | N idx]
    const int N = in_sizes[0] / D;              // 131072

    esq_kernel<<<(KCODES + 255) / 256, 256>>>(emb);
    const int nb = (N + BLOCK - 1) / BLOCK;     // 512
    vq_kernel<<<nb, BLOCK>>>(x, emb, out, N);
    loss_kernel<<<1, 512>>>(out, nb, N);
}

// round 2
// speedup vs baseline: 1.0015x; 1.0015x over previous
#include <cuda_runtime.h>

#define D        64
#define KCODES   1024
#define TK       128      // codes per smem tile (128*64*4 = 32 KB)
#define BLOCK    256

// Scratch (allocation-free rule: __device__ globals)
__device__ float g_esq[KCODES];
__device__ float g_partials[1024];

// ---------------------------------------------------------------------------
// packed f32x2 helpers (FFMA2 path — only reachable via PTX, not from C++)
// ---------------------------------------------------------------------------
__device__ __forceinline__ void ffma2(unsigned long long& d,
                                      unsigned long long a,
                                      unsigned long long b) {
    asm("fma.rn.f32x2 %0, %1, %2, %0;" : "+l"(d) : "l"(a), "l"(b));
}
__device__ __forceinline__ void fadd2(unsigned long long& d,
                                      unsigned long long a) {
    asm("add.rn.f32x2 %0, %0, %1;" : "+l"(d) : "l"(a));
}

// ---------------------------------------------------------------------------
// Kernel 0: |e_k|^2 for every code
// ---------------------------------------------------------------------------
__global__ void esq_kernel(const float* __restrict__ emb) {
    int k = blockIdx.x * blockDim.x + threadIdx.x;
    if (k < KCODES) {
        const float4* e = (const float4*)(emb + (size_t)k * D);
        float s = 0.f;
#pragma unroll
        for (int i = 0; i < D / 4; i++) {
            float4 v = e[i];
            s += v.x * v.x + v.y * v.y + v.z * v.z + v.w * v.w;
        }
        g_esq[k] = s;
    }
}

// ---------------------------------------------------------------------------
// Kernel 1: per-row argmin over K codes + quant gather + indices + partial loss
// ---------------------------------------------------------------------------
__global__ __launch_bounds__(BLOCK, 2) void vq_kernel(
    const float* __restrict__ x, const float* __restrict__ emb,
    float* __restrict__ out, int N)
{
    __shared__ __align__(16) float s_e[TK * D];
    __shared__ float s_esq[TK];
    __shared__ float s_red[BLOCK / 32];

    const int row    = blockIdx.x * BLOCK + threadIdx.x;
    const bool valid = (row < N);

    // ---- load my row as 32 packed f32x2 operands ----
    unsigned long long xp[32];
    float xsq = 0.f;
    if (valid) {
        const ulonglong2* xr = (const ulonglong2*)(x + (size_t)row * D);
#pragma unroll
        for (int i = 0; i < 16; i++) {
            ulonglong2 v = xr[i];
            xp[2 * i]     = v.x;
            xp[2 * i + 1] = v.y;
        }
#pragma unroll
        for (int j = 0; j < 32; j++) {
            float2 f = *(float2*)&xp[j];
            xsq += f.x * f.x + f.y * f.y;
        }
    } else {
#pragma unroll
        for (int j = 0; j < 32; j++) xp[j] = 0ull;
    }

    float best = 3.402823466e38f;
    int   bidx = 0;

    for (int t0 = 0; t0 < KCODES; t0 += TK) {
        __syncthreads();
        // cooperative tile load: TK codes, contiguous 32 KB copy
        {
            const float4* src = (const float4*)(emb + (size_t)t0 * D);
            float4* dst = (float4*)s_e;
            for (int i = threadIdx.x; i < TK * D / 4; i += BLOCK) dst[i] = src[i];
            if (threadIdx.x < TK) s_esq[threadIdx.x] = g_esq[t0 + threadIdx.x];
        }
        __syncthreads();

#pragma unroll 2
        for (int kk = 0; kk < TK; kk++) {
            const ulonglong2* er = (const ulonglong2*)(s_e + kk * D);
            unsigned long long a0 = 0ull, a1 = 0ull, a2 = 0ull, a3 = 0ull;
#pragma unroll
            for (int i = 0; i < 16; i++) {
                ulonglong2 ev = er[i];   // broadcast LDS.128 (uniform addr)
                if (i & 1) { ffma2(a2, xp[2 * i], ev.x); ffma2(a3, xp[2 * i + 1], ev.y); }
                else       { ffma2(a0, xp[2 * i], ev.x); ffma2(a1, xp[2 * i + 1], ev.y); }
            }
            fadd2(a0, a2); fadd2(a1, a3); fadd2(a0, a1);
            float2 dp  = *(float2*)&a0;
            float  dot = dp.x + dp.y;
            // mirror reference: (input_sq + embed_sq) - 2*dot, same rounding/ties
            float dist = (xsq + s_esq[kk]) - 2.0f * dot;
            if (dist < best) { best = dist; bidx = t0 + kk; }
        }
    }

    // ---- epilogue: gather quant, write index, accumulate (q - x)^2 ----
    float errsum = 0.f;
    if (valid) {
        const float4* eb = (const float4*)(emb + (size_t)bidx * D);
        float4* oq = (float4*)(out + (size_t)row * D);
#pragma unroll
        for (int i = 0; i < 16; i++) {
            float4 e = eb[i];
            oq[i] = e;                            // quant_st == embedding[idx]
            float2 a = *(float2*)&xp[2 * i];
            float2 b = *(float2*)&xp[2 * i + 1];
            float d0 = e.x - a.x, d1 = e.y - a.y;
            float d2 = e.z - b.x, d3 = e.w - b.y;
            errsum += d0 * d0 + d1 * d1 + d2 * d2 + d3 * d3;
        }
        out[(size_t)N * D + 1 + row] = (float)bidx;  // encoding index as f32
    }

    // deterministic block reduction of errsum
#pragma unroll
    for (int o = 16; o; o >>= 1) errsum += __shfl_down_sync(0xffffffffu, errsum, o);
    if ((threadIdx.x & 31) == 0) s_red[threadIdx.x >> 5] = errsum;
    __syncthreads();
    if (threadIdx.x < 32) {
        float v = (threadIdx.x < BLOCK / 32) ? s_red[threadIdx.x] : 0.f;
#pragma unroll
        for (int o = 4; o; o >>= 1) v += __shfl_down_sync(0xffffffffu, v, o);
        if (threadIdx.x == 0) g_partials[blockIdx.x] = v;
    }
}

// ---------------------------------------------------------------------------
// Kernel 2: deterministic final loss reduction
// ---------------------------------------------------------------------------
__global__ void loss_kernel(float* __restrict__ out, int nblocks, int N) {
    __shared__ float s_red[16];
    float v = 0.f;
    for (int i = threadIdx.x; i < nblocks; i += blockDim.x) v += g_partials[i];
#pragma unroll
    for (int o = 16; o; o >>= 1) v += __shfl_down_sync(0xffffffffu, v, o);
    if ((threadIdx.x & 31) == 0) s_red[threadIdx.x >> 5] = v;
    __syncthreads();
    if (threadIdx.x < 32) {
        float t = (threadIdx.x < (int)(blockDim.x / 32)) ? s_red[threadIdx.x] : 0.f;
#pragma unroll
        for (int o = 8; o; o >>= 1) t += __shfl_down_sync(0xffffffffu, t, o);
        if (threadIdx.x == 0) {
            // loss = q_latent + 0.25 * e_latent = 1.25 * mean((q - x)^2)
            out[(size_t)N * D] = 1.25f * t / ((float)N * (float)D);
        }
    }
}

// ---------------------------------------------------------------------------
extern "C" void kernel_launch(void* const* d_in, const int* in_sizes, int n_in,
                              void* d_out, int out_size) {
    const float* x   = (const float*)d_in[0];   // inputs  [B,T,D] fp32
    const float* emb = (const float*)d_in[1];   // embedding [K,D] fp32
    float* out = (float*)d_out;                 // [N*D quant | 1 loss | N idx]
    const int N = in_sizes[0] / D;              // 131072

    esq_kernel<<<(KCODES + 255) / 256, 256>>>(emb);
    const int nb = (N + BLOCK - 1) / BLOCK;     // 512
    vq_kernel<<<nb, BLOCK>>>(x, emb, out, N);
    loss_kernel<<<1, 512>>>(out, nb, N);
}

// round 6
// speedup vs baseline: 2.0786x; 2.0755x over previous
#include <cuda_runtime.h>
#include <cuda_bf16.h>
#include <cstdint>

#define DDIM    64
#define KCODES  1024
#define NCHUNK  8
#define CPC     128          // codes per chunk
#define NSUB    4            // subtiles (n32) per chunk
#define BLOCK   256          // 8 warps, 256 rows per block
#define RESCORE_TAU 2e-3f

// ---------------- device scratch (allocation-free rule) ----------------
__device__ float g_esq[KCODES];
// fragment-ordered codebook: [chunk][level(h,m)][ks(4)][ntile(16)][lane(32)] -> {b0,b1}
__device__ uint2 g_bfrag[NCHUNK][2][4][16][32];     // 256 KB
__device__ float g_partials[512];

// ---------------- helpers ----------------
__device__ __forceinline__ uint32_t packbf(float lo, float hi) {
    __nv_bfloat162 h = __floats2bfloat162_rn(lo, hi);
    return *reinterpret_cast<uint32_t*>(&h);
}
// split pair into bf16 hi + bf16 mid(residual)
__device__ __forceinline__ void split2(float a, float b, uint32_t& h, uint32_t& m) {
    __nv_bfloat16 ha = __float2bfloat16(a), hb = __float2bfloat16(b);
    float ra = a - __bfloat162float(ha);
    float rb = b - __bfloat162float(hb);
    h = packbf(__bfloat162float(ha), __bfloat162float(hb));
    m = packbf(ra, rb);
}
#define MMA16816(D, A, b0v, b1v)                                             \
    asm volatile("mma.sync.aligned.m16n8k16.row.col.f32.bf16.bf16.f32 "      \
                 "{%0,%1,%2,%3}, {%4,%5,%6,%7}, {%8,%9}, {%0,%1,%2,%3};"     \
                 : "+f"((D)[0]), "+f"((D)[1]), "+f"((D)[2]), "+f"((D)[3])    \
                 : "r"((A)[0]), "r"((A)[1]), "r"((A)[2]), "r"((A)[3]),       \
                   "r"(b0v), "r"(b1v))

// reference-coarse distance: fl32(fl32(xsq+esq) - fl32(2*dot))
__device__ __forceinline__ float coarse_dist(float xsq, float esq, float dotf) {
    float t = __fadd_rn(xsq, esq);
    return __fadd_rn(t, -__fmul_rn(2.0f, dotf));
}

// ---------------- prep: |e|^2 ----------------
__global__ void prep_esq(const float* __restrict__ emb) {
    int k = blockIdx.x * blockDim.x + threadIdx.x;
    if (k >= KCODES) return;
    const float4* e = (const float4*)(emb + (size_t)k * DDIM);
    float s = 0.f;
#pragma unroll
    for (int i = 0; i < 16; i++) {
        float4 v = e[i];
        s += v.x * v.x + v.y * v.y + v.z * v.z + v.w * v.w;
    }
    g_esq[k] = s;
}

// ---------------- prep: codebook -> mma B fragments (hi & mid bf16) ----------------
__global__ void prep_frag(const float* __restrict__ emb) {
    int idx = blockIdx.x * blockDim.x + threadIdx.x;   // 16384 total
    int lane = idx & 31;
    int ntg  = (idx >> 5) & 15;
    int ks   = (idx >> 9) & 3;
    int c    = idx >> 11;
    if (c >= NCHUNK) return;
    int g = lane >> 2, t = lane & 3;
    int n = c * CPC + ntg * 8 + g;
    const float* e = emb + (size_t)n * DDIM + ks * 16;
    uint32_t h0, m0, h1, m1;
    split2(e[2 * t],     e[2 * t + 1], h0, m0);
    split2(e[2 * t + 8], e[2 * t + 9], h1, m1);
    g_bfrag[c][0][ks][ntg][lane] = make_uint2(h0, h1);
    g_bfrag[c][1][ks][ntg][lane] = make_uint2(m0, m1);
}

// ---------------- main kernel ----------------
__global__ __launch_bounds__(BLOCK) void vq_main(
    const float* __restrict__ x, const float* __restrict__ emb,
    float* __restrict__ out, int N)
{
    __shared__ uint2 s_bfrag[2][4][16][32];   // 32 KB, chunk-resident fragments
    __shared__ float s_esq[CPC];
    __shared__ float s_red[BLOCK / 32];

    const int tid = threadIdx.x, wid = tid >> 5, lane = tid & 31;
    const int g = lane >> 2, t = lane & 3;
    const int base = blockIdx.x * BLOCK + wid * 32;   // 32 rows per warp

    // ---- load A fragments (resident): hi + mid bf16, [mt][ks][a0..a3] ----
    uint32_t Ah[2][4][4], Am[2][4][4];
#pragma unroll
    for (int mt = 0; mt < 2; mt++) {
        const float* r0 = x + (size_t)(base + mt * 16 + g) * DDIM;
        const float* r8 = r0 + 8 * DDIM;
#pragma unroll
        for (int ks = 0; ks < 4; ks++) {
            const float2* p0 = (const float2*)(r0 + ks * 16);
            const float2* p8 = (const float2*)(r8 + ks * 16);
            float2 v0a = p0[t], v0b = p0[t + 4];
            float2 v8a = p8[t], v8b = p8[t + 4];
            split2(v0a.x, v0a.y, Ah[mt][ks][0], Am[mt][ks][0]);
            split2(v8a.x, v8a.y, Ah[mt][ks][1], Am[mt][ks][1]);
            split2(v0b.x, v0b.y, Ah[mt][ks][2], Am[mt][ks][2]);
            split2(v8b.x, v8b.y, Ah[mt][ks][3], Am[mt][ks][3]);
        }
    }

    float b1[4] = {3.4e38f, 3.4e38f, 3.4e38f, 3.4e38f};
    float b2[4] = {3.4e38f, 3.4e38f, 3.4e38f, 3.4e38f};
    int   i1[4] = {0, 0, 0, 0}, i2[4] = {0, 0, 0, 0};

    for (int c = 0; c < NCHUNK; c++) {
        __syncthreads();
        {   // cooperative chunk load: 32 KB fragments + esq
            const uint4* src = (const uint4*)&g_bfrag[c][0][0][0][0];
            uint4* dst = (uint4*)s_bfrag;
#pragma unroll
            for (int i = 0; i < 8; i++) dst[tid + BLOCK * i] = src[tid + BLOCK * i];
            if (tid < CPC) s_esq[tid] = g_esq[c * CPC + tid];
        }
        __syncthreads();

        for (int sub = 0; sub < NSUB; sub++) {
            float acc[2][4][4];
#pragma unroll
            for (int mt = 0; mt < 2; mt++)
#pragma unroll
                for (int nt = 0; nt < 4; nt++)
#pragma unroll
                    for (int q = 0; q < 4; q++) acc[mt][nt][q] = 0.f;

            // 3 passes: xh*eh, xh*em, xm*eh
#pragma unroll
            for (int pass = 0; pass < 3; pass++) {
                const int blvl = (pass == 1) ? 1 : 0;
                uint32_t (*A)[4][4] = (pass == 2) ? Am : Ah;
#pragma unroll
                for (int ks = 0; ks < 4; ks++) {
                    uint2 b[4];
#pragma unroll
                    for (int nt = 0; nt < 4; nt++)
                        b[nt] = s_bfrag[blvl][ks][sub * 4 + nt][lane];
#pragma unroll
                    for (int nt = 0; nt < 4; nt++) {
                        MMA16816(acc[0][nt], A[0][ks], b[nt].x, b[nt].y);
                        MMA16816(acc[1][nt], A[1][ks], b[nt].x, b[nt].y);
                    }
                }
            }

            // epilogue: fine dist = esq - 2*dot, top-2 per row
#pragma unroll
            for (int nt = 0; nt < 4; nt++) {
                const int ntg = sub * 4 + nt;
                float2 es = *(const float2*)&s_esq[ntg * 8 + 2 * t];
                const int k0 = c * CPC + ntg * 8 + 2 * t;
#pragma unroll
                for (int mt = 0; mt < 2; mt++) {
#pragma unroll
                    for (int h = 0; h < 2; h++) {       // h=0: row g, h=1: row g+8
                        const int j = mt * 2 + h;
                        float d0 = fmaf(-2.f, acc[mt][nt][h * 2],     es.x);
                        float d1 = fmaf(-2.f, acc[mt][nt][h * 2 + 1], es.y);
                        bool p1 = d0 < b1[j], p2 = d0 < b2[j];
                        b2[j] = p1 ? b1[j] : (p2 ? d0 : b2[j]);
                        i2[j] = p1 ? i1[j] : (p2 ? k0 : i2[j]);
                        b1[j] = p1 ? d0 : b1[j];
                        i1[j] = p1 ? k0 : i1[j];
                        p1 = d1 < b1[j]; p2 = d1 < b2[j];
                        b2[j] = p1 ? b1[j] : (p2 ? d1 : b2[j]);
                        i2[j] = p1 ? i1[j] : (p2 ? (k0 + 1) : i2[j]);
                        b1[j] = p1 ? d1 : b1[j];
                        i1[j] = p1 ? (k0 + 1) : i1[j];
                    }
                }
            }
        }
    }

    // ---- merge top-2 across the 4-lane t-group ----
#pragma unroll
    for (int off = 1; off <= 2; off <<= 1) {
#pragma unroll
        for (int j = 0; j < 4; j++) {
            float ob1 = __shfl_xor_sync(0xffffffffu, b1[j], off);
            int   oi1 = __shfl_xor_sync(0xffffffffu, i1[j], off);
            float ob2 = __shfl_xor_sync(0xffffffffu, b2[j], off);
            int   oi2 = __shfl_xor_sync(0xffffffffu, i2[j], off);
            bool pa = (ob1 < b1[j]) || (ob1 == b1[j] && oi1 < i1[j]);
            float nb1 = pa ? ob1 : b1[j];  int ni1 = pa ? oi1 : i1[j];
            float hi  = pa ? b1[j] : ob1;  int ih  = pa ? i1[j] : oi1;
            bool pb = (ob2 < b2[j]) || (ob2 == b2[j] && oi2 < i2[j]);
            float mn2 = pb ? ob2 : b2[j];  int im2 = pb ? oi2 : i2[j];
            bool pc = (hi < mn2) || (hi == mn2 && ih < im2);
            b1[j] = nb1; i1[j] = ni1;
            b2[j] = pc ? hi : mn2; i2[j] = pc ? ih : im2;
        }
    }

    // ---- near-tie rescore (~750/131072 rows): replicate the REFERENCE's
    //      coarse fp32 arithmetic. xsq at magnitude ~62 quantizes distances
    //      to a ~4e-6 grid; ties on that grid go to the LOWER index, exactly
    //      like jnp.argmin over fp32 distances. dot via fp64 -> fp32. ----
#pragma unroll
    for (int j = 0; j < 4; j++) {
        if (b2[j] - b1[j] < RESCORE_TAU) {
            const int row = base + (j >> 1) * 16 + (j & 1) * 8 + g;
            const float* xr = x + (size_t)row * DDIM;
            const float* e1 = emb + (size_t)i1[j] * DDIM;
            const float* e2 = emb + (size_t)i2[j] * DDIM;
            // xsq: sequential fp32, no FMA (XLA-style row reduce of flat**2)
            float xsq = 0.f;
            for (int k = 0; k < DDIM; k++)
                xsq = __fadd_rn(xsq, __fmul_rn(xr[k], xr[k]));
            double dd1 = 0.0, dd2 = 0.0;
            for (int k = 0; k < DDIM; k++) {
                double xv = (double)xr[k];
                dd1 = fma(xv, (double)e1[k], dd1);
                dd2 = fma(xv, (double)e2[k], dd2);
            }
            float c1 = coarse_dist(xsq, g_esq[i1[j]], (float)dd1);
            float c2 = coarse_dist(xsq, g_esq[i2[j]], (float)dd2);
            if (c2 < c1 || (c2 == c1 && i2[j] < i1[j])) i1[j] = i2[j];
        }
    }

    // ---- outputs: quant gather (exact fp32), indices, exact loss partial ----
    float errsum = 0.f;
#pragma unroll
    for (int j = 0; j < 4; j++) {
        const int row = base + (j >> 1) * 16 + (j & 1) * 8 + g;
        const int idx = i1[j];
        if (t == 0) out[(size_t)N * DDIM + 1 + row] = (float)idx;
        const float4* ep = (const float4*)(emb + (size_t)idx * DDIM + t * 16);
        const float4* xp = (const float4*)(x + (size_t)row * DDIM + t * 16);
        float4* op = (float4*)(out + (size_t)row * DDIM + t * 16);
#pragma unroll
        for (int q = 0; q < 4; q++) {
            float4 e = ep[q], v = xp[q];
            op[q] = e;
            float d0 = e.x - v.x, d1 = e.y - v.y, d2 = e.z - v.z, d3 = e.w - v.w;
            errsum += d0 * d0 + d1 * d1 + d2 * d2 + d3 * d3;
        }
    }
#pragma unroll
    for (int o = 16; o; o >>= 1) errsum += __shfl_down_sync(0xffffffffu, errsum, o);
    if (lane == 0) s_red[wid] = errsum;
    __syncthreads();
    if (tid == 0) {
        float s = 0.f;
#pragma unroll
        for (int w = 0; w < BLOCK / 32; w++) s += s_red[w];
        g_partials[blockIdx.x] = s;
    }
}

// ---------------- final loss reduction ----------------
__global__ void loss_kernel(float* __restrict__ out, int nblocks, int N) {
    __shared__ float s_red[16];
    float v = 0.f;
    for (int i = threadIdx.x; i < nblocks; i += blockDim.x) v += g_partials[i];
#pragma unroll
    for (int o = 16; o; o >>= 1) v += __shfl_down_sync(0xffffffffu, v, o);
    if ((threadIdx.x & 31) == 0) s_red[threadIdx.x >> 5] = v;
    __syncthreads();
    if (threadIdx.x < 32) {
        float tt = (threadIdx.x < (int)(blockDim.x / 32)) ? s_red[threadIdx.x] : 0.f;
#pragma unroll
        for (int o = 8; o; o >>= 1) tt += __shfl_down_sync(0xffffffffu, tt, o);
        if (threadIdx.x == 0)
            out[(size_t)N * DDIM] = 1.25f * tt / ((float)N * (float)DDIM);
    }
}

// ---------------------------------------------------------------------------
extern "C" void kernel_launch(void* const* d_in, const int* in_sizes, int n_in,
                              void* d_out, int out_size) {
    const float* x   = (const float*)d_in[0];   // [B,T,D] fp32
    const float* emb = (const float*)d_in[1];   // [K,D]  fp32
    float* out = (float*)d_out;                 // [N*D quant | 1 loss | N idx]
    const int N  = in_sizes[0] / DDIM;          // 131072
    const int nb = N / BLOCK;                   // 512

    prep_esq<<<(KCODES + 255) / 256, 256>>>(emb);
    prep_frag<<<64, 256>>>(emb);
    vq_main<<<nb, BLOCK>>>(x, emb, out, N);
    loss_kernel<<<1, 512>>>(out, nb, N);
}

// round 8
// speedup vs baseline: 2.5260x; 1.2152x over previous
#include <cuda_runtime.h>
#include <cuda_bf16.h>
#include <cstdint>

#define DDIM    64
#define KCODES  1024
#define NCHUNK  8
#define CPC     128          // codes per chunk
#define NSUB    4            // subtiles (n32) per chunk
#define BLOCK   256          // 8 warps, 256 rows per block
#define RESCORE_TAU 2e-3f

// ---------------- device scratch (allocation-free rule) ----------------
__device__ float g_esq[KCODES];
// fragment-ordered codebook: [chunk][level(h,m)][ks(4)][ntile(16)][lane(32)] -> {b0,b1}
__device__ uint2 g_bfrag[NCHUNK][2][4][16][32];     // 256 KB
__device__ float g_partials[512];

// ---------------- helpers ----------------
__device__ __forceinline__ uint32_t packbf(float lo, float hi) {
    __nv_bfloat162 h = __floats2bfloat162_rn(lo, hi);
    return *reinterpret_cast<uint32_t*>(&h);
}
__device__ __forceinline__ void split2(float a, float b, uint32_t& h, uint32_t& m) {
    __nv_bfloat16 ha = __float2bfloat16(a), hb = __float2bfloat16(b);
    float ra = a - __bfloat162float(ha);
    float rb = b - __bfloat162float(hb);
    h = packbf(__bfloat162float(ha), __bfloat162float(hb));
    m = packbf(ra, rb);
}
#define MMA16816(D, A, b0v, b1v)                                             \
    asm volatile("mma.sync.aligned.m16n8k16.row.col.f32.bf16.bf16.f32 "      \
                 "{%0,%1,%2,%3}, {%4,%5,%6,%7}, {%8,%9}, {%0,%1,%2,%3};"     \
                 : "+f"((D)[0]), "+f"((D)[1]), "+f"((D)[2]), "+f"((D)[3])    \
                 : "r"((A)[0]), "r"((A)[1]), "r"((A)[2]), "r"((A)[3]),       \
                   "r"(b0v), "r"(b1v))

#define CP_ASYNC16(saddr, gptr) \
    asm volatile("cp.async.cg.shared.global [%0], [%1], 16;" :: "r"(saddr), "l"(gptr) : "memory")
#define CP_COMMIT() asm volatile("cp.async.commit_group;" ::: "memory")
#define CP_WAIT0()  asm volatile("cp.async.wait_group 0;" ::: "memory")

__device__ __forceinline__ uint32_t smem_u32(const void* p) {
    uint32_t a;
    asm("{ .reg .u64 t; cvta.to.shared.u64 t, %1; cvt.u32.u64 %0, t; }" : "=r"(a) : "l"(p));
    return a;
}

// reference-coarse distance: fl32(fl32(xsq+esq) - fl32(2*dot))
__device__ __forceinline__ float coarse_dist(float xsq, float esq, float dotf) {
    float t = __fadd_rn(xsq, esq);
    return __fadd_rn(t, -__fmul_rn(2.0f, dotf));
}
// embed 7-bit local code into low mantissa bits
__device__ __forceinline__ float keyed(float d, uint32_t code) {
    return __uint_as_float((__float_as_uint(d) & 0xFFFFFF80u) | code);
}

// ---------------- prep: |e|^2 ----------------
__global__ void prep_esq(const float* __restrict__ emb) {
    int k = blockIdx.x * blockDim.x + threadIdx.x;
    if (k >= KCODES) return;
    const float4* e = (const float4*)(emb + (size_t)k * DDIM);
    float s = 0.f;
#pragma unroll
    for (int i = 0; i < 16; i++) {
        float4 v = e[i];
        s += v.x * v.x + v.y * v.y + v.z * v.z + v.w * v.w;
    }
    g_esq[k] = s;
}

// ---------------- prep: codebook -> mma B fragments (hi & mid bf16) ----------------
__global__ void prep_frag(const float* __restrict__ emb) {
    int idx = blockIdx.x * blockDim.x + threadIdx.x;   // 16384 total
    int lane = idx & 31;
    int ntg  = (idx >> 5) & 15;
    int ks   = (idx >> 9) & 3;
    int c    = idx >> 11;
    if (c >= NCHUNK) return;
    int g = lane >> 2, t = lane & 3;
    int n = c * CPC + ntg * 8 + g;
    const float* e = emb + (size_t)n * DDIM + ks * 16;
    uint32_t h0, m0, h1, m1;
    split2(e[2 * t],     e[2 * t + 1], h0, m0);
    split2(e[2 * t + 8], e[2 * t + 9], h1, m1);
    g_bfrag[c][0][ks][ntg][lane] = make_uint2(h0, h1);
    g_bfrag[c][1][ks][ntg][lane] = make_uint2(m0, m1);
}

// ---------------- main kernel ----------------
// dynamic smem: [2 bufs x 32KB bfrag][1024 f32 esq][8 f32 red]
#define OFF_BFRAG 0
#define OFF_ESQ   65536
#define OFF_RED   69632
#define SMEM_SZ   69664
#define BUF_U2    4096        // 32 KB buffer stride in uint2 ELEMENTS

__global__ __launch_bounds__(BLOCK, 2) void vq_main(
    const float* __restrict__ x, const float* __restrict__ emb,
    float* __restrict__ out, int N)
{
    extern __shared__ char smem[];
    uint2* s_bfrag = (uint2*)(smem + OFF_BFRAG);       // [buf][blvl][ks][ntg][lane]
    float* s_esq   = (float*)(smem + OFF_ESQ);
    float* s_red   = (float*)(smem + OFF_RED);
    const uint32_t sb_frag = smem_u32(s_bfrag);

    const int tid = threadIdx.x, wid = tid >> 5, lane = tid & 31;
    const int g = lane >> 2, t = lane & 3;
    const int base = blockIdx.x * BLOCK + wid * 32;    // 32 rows per warp

    // ---- load A fragments (resident): hi + mid bf16 ----
    uint32_t Ah[2][4][4], Am[2][4][4];
#pragma unroll
    for (int mt = 0; mt < 2; mt++) {
        const float* r0 = x + (size_t)(base + mt * 16 + g) * DDIM;
        const float* r8 = r0 + 8 * DDIM;
#pragma unroll
        for (int ks = 0; ks < 4; ks++) {
            const float2* p0 = (const float2*)(r0 + ks * 16);
            const float2* p8 = (const float2*)(r8 + ks * 16);
            float2 v0a = p0[t], v0b = p0[t + 4];
            float2 v8a = p8[t], v8b = p8[t + 4];
            split2(v0a.x, v0a.y, Ah[mt][ks][0], Am[mt][ks][0]);
            split2(v8a.x, v8a.y, Ah[mt][ks][1], Am[mt][ks][1]);
            split2(v0b.x, v0b.y, Ah[mt][ks][2], Am[mt][ks][2]);
            split2(v8b.x, v8b.y, Ah[mt][ks][3], Am[mt][ks][3]);
        }
    }

    // ---- esq (all 1024, loaded once) + prefetch chunk 0 ----
    {
        const char* src = (const char*)&g_bfrag[0][0][0][0][0];
#pragma unroll
        for (int i = 0; i < 8; i++)
            CP_ASYNC16(sb_frag + tid * 16 + i * 4096, src + tid * 16 + i * 4096);
        CP_COMMIT();
        for (int i = tid; i < KCODES; i += BLOCK) s_esq[i] = g_esq[i];
    }
    CP_WAIT0();
    __syncthreads();

    float gb1[4] = {3.4e38f, 3.4e38f, 3.4e38f, 3.4e38f};
    float gb2[4] = {3.4e38f, 3.4e38f, 3.4e38f, 3.4e38f};
    int   gi1[4] = {0, 0, 0, 0}, gi2[4] = {0, 0, 0, 0};

    for (int c = 0; c < NCHUNK; c++) {
        const int cur = c & 1;
        if (c < NCHUNK - 1) {   // prefetch next chunk into other buffer
            const char* src = (const char*)&g_bfrag[c + 1][0][0][0][0];
            const uint32_t dst = sb_frag + (cur ^ 1) * 32768;   // byte offset
#pragma unroll
            for (int i = 0; i < 8; i++)
                CP_ASYNC16(dst + tid * 16 + i * 4096, src + tid * 16 + i * 4096);
            CP_COMMIT();
        }
        const uint2* bf = s_bfrag + cur * BUF_U2;      // FIXED: element stride (was *8192 = 64KB OOB)

        // chunk-local keyed top-2 (7-bit embedded code)
        float fc1[4] = {3.4e38f, 3.4e38f, 3.4e38f, 3.4e38f};
        float fc2[4] = {3.4e38f, 3.4e38f, 3.4e38f, 3.4e38f};

        for (int sub = 0; sub < NSUB; sub++) {
            float acc[2][4][4];
#pragma unroll
            for (int mt = 0; mt < 2; mt++)
#pragma unroll
                for (int nt = 0; nt < 4; nt++)
#pragma unroll
                    for (int q = 0; q < 4; q++) acc[mt][nt][q] = 0.f;

            // 3 passes: xh*eh, xh*em, xm*eh
#pragma unroll
            for (int pass = 0; pass < 3; pass++) {
                const int blvl = (pass == 1) ? 1 : 0;
                uint32_t (*A)[4][4] = (pass == 2) ? Am : Ah;
#pragma unroll
                for (int ks = 0; ks < 4; ks++) {
                    uint2 b[4];
#pragma unroll
                    for (int nt = 0; nt < 4; nt++)
                        b[nt] = bf[((blvl * 4 + ks) * 16 + sub * 4 + nt) * 32 + lane];
#pragma unroll
                    for (int nt = 0; nt < 4; nt++) {
                        MMA16816(acc[0][nt], A[0][ks], b[nt].x, b[nt].y);
                        MMA16816(acc[1][nt], A[1][ks], b[nt].x, b[nt].y);
                    }
                }
            }

            // epilogue: dist = esq - 2*dot, keyed top-2 (5 instr/dist)
#pragma unroll
            for (int nt = 0; nt < 4; nt++) {
                const int ntg = sub * 4 + nt;
                float2 es = *(const float2*)&s_esq[c * CPC + ntg * 8 + 2 * t];
                const uint32_t lc = (uint32_t)(ntg * 8 + 2 * t);
#pragma unroll
                for (int mt = 0; mt < 2; mt++) {
#pragma unroll
                    for (int h = 0; h < 2; h++) {
                        const int j = mt * 2 + h;
                        float f0 = keyed(fmaf(-2.f, acc[mt][nt][h * 2],     es.x), lc);
                        float f1 = keyed(fmaf(-2.f, acc[mt][nt][h * 2 + 1], es.y), lc + 1);
                        float t0 = fmaxf(fc1[j], f0);
                        fc2[j] = fminf(fc2[j], t0);
                        fc1[j] = fminf(fc1[j], f0);
                        float t1 = fmaxf(fc1[j], f1);
                        fc2[j] = fminf(fc2[j], t1);
                        fc1[j] = fminf(fc1[j], f1);
                    }
                }
            }
        }

        // fold chunk winners into global float top-2 (exact compare, idx tie-break)
#pragma unroll
        for (int j = 0; j < 4; j++) {
#pragma unroll
            for (int w = 0; w < 2; w++) {
                uint32_t bits = __float_as_uint(w ? fc2[j] : fc1[j]);
                float f = __uint_as_float(bits & 0xFFFFFF80u);
                int   i = c * CPC + (int)(bits & 127u);
                bool p1 = (f < gb1[j]) || (f == gb1[j] && i < gi1[j]);
                bool p2 = (f < gb2[j]) || (f == gb2[j] && i < gi2[j]);
                gb2[j] = p1 ? gb1[j] : (p2 ? f : gb2[j]);
                gi2[j] = p1 ? gi1[j] : (p2 ? i : gi2[j]);
                gb1[j] = p1 ? f : gb1[j];
                gi1[j] = p1 ? i : gi1[j];
            }
        }

        if (c < NCHUNK - 1) CP_WAIT0();
        __syncthreads();
    }

    // ---- merge top-2 across the 4-lane t-group ----
#pragma unroll
    for (int off = 1; off <= 2; off <<= 1) {
#pragma unroll
        for (int j = 0; j < 4; j++) {
            float ob1 = __shfl_xor_sync(0xffffffffu, gb1[j], off);
            int   oi1 = __shfl_xor_sync(0xffffffffu, gi1[j], off);
            float ob2 = __shfl_xor_sync(0xffffffffu, gb2[j], off);
            int   oi2 = __shfl_xor_sync(0xffffffffu, gi2[j], off);
            bool pa = (ob1 < gb1[j]) || (ob1 == gb1[j] && oi1 < gi1[j]);
            float nb1 = pa ? ob1 : gb1[j];  int ni1 = pa ? oi1 : gi1[j];
            float hi  = pa ? gb1[j] : ob1;  int ih  = pa ? gi1[j] : oi1;
            bool pb = (ob2 < gb2[j]) || (ob2 == gb2[j] && oi2 < gi2[j]);
            float mn2 = pb ? ob2 : gb2[j];  int im2 = pb ? oi2 : gi2[j];
            bool pc = (hi < mn2) || (hi == mn2 && ih < im2);
            gb1[j] = nb1; gi1[j] = ni1;
            gb2[j] = pc ? hi : mn2; gi2[j] = pc ? ih : im2;
        }
    }

    // ---- near-tie rescore: replicate the REFERENCE's coarse fp32 arithmetic ----
#pragma unroll
    for (int j = 0; j < 4; j++) {
        if (gb2[j] - gb1[j] < RESCORE_TAU) {
            const int row = base + (j >> 1) * 16 + (j & 1) * 8 + g;
            const float* xr = x + (size_t)row * DDIM;
            const float* e1 = emb + (size_t)gi1[j] * DDIM;
            const float* e2 = emb + (size_t)gi2[j] * DDIM;
            float xsq = 0.f;
            for (int k = 0; k < DDIM; k++)
                xsq = __fadd_rn(xsq, __fmul_rn(xr[k], xr[k]));
            double dd1 = 0.0, dd2 = 0.0;
            for (int k = 0; k < DDIM; k++) {
                double xv = (double)xr[k];
                dd1 = fma(xv, (double)e1[k], dd1);
                dd2 = fma(xv, (double)e2[k], dd2);
            }
            float c1 = coarse_dist(xsq, g_esq[gi1[j]], (float)dd1);
            float c2 = coarse_dist(xsq, g_esq[gi2[j]], (float)dd2);
            if (c2 < c1 || (c2 == c1 && gi2[j] < gi1[j])) gi1[j] = gi2[j];
        }
    }

    // ---- outputs: quant gather (exact fp32), indices, exact loss partial ----
    float errsum = 0.f;
#pragma unroll
    for (int j = 0; j < 4; j++) {
        const int row = base + (j >> 1) * 16 + (j & 1) * 8 + g;
        const int idx = gi1[j];
        if (t == 0) out[(size_t)N * DDIM + 1 + row] = (float)idx;
        const float4* ep = (const float4*)(emb + (size_t)idx * DDIM + t * 16);
        const float4* xp = (const float4*)(x + (size_t)row * DDIM + t * 16);
        float4* op = (float4*)(out + (size_t)row * DDIM + t * 16);
#pragma unroll
        for (int q = 0; q < 4; q++) {
            float4 e = ep[q], v = xp[q];
            op[q] = e;
            float d0 = e.x - v.x, d1 = e.y - v.y, d2 = e.z - v.z, d3 = e.w - v.w;
            errsum += d0 * d0 + d1 * d1 + d2 * d2 + d3 * d3;
        }
    }
#pragma unroll
    for (int o = 16; o; o >>= 1) errsum += __shfl_down_sync(0xffffffffu, errsum, o);
    if (lane == 0) s_red[wid] = errsum;
    __syncthreads();
    if (tid == 0) {
        float s = 0.f;
#pragma unroll
        for (int w = 0; w < BLOCK / 32; w++) s += s_red[w];
        g_partials[blockIdx.x] = s;
    }
}

// ---------------- final loss reduction ----------------
__global__ void loss_kernel(float* __restrict__ out, int nblocks, int N) {
    __shared__ float s_red[16];
    float v = 0.f;
    for (int i = threadIdx.x; i < nblocks; i += blockDim.x) v += g_partials[i];
#pragma unroll
    for (int o = 16; o; o >>= 1) v += __shfl_down_sync(0xffffffffu, v, o);
    if ((threadIdx.x & 31) == 0) s_red[threadIdx.x >> 5] = v;
    __syncthreads();
    if (threadIdx.x < 32) {
        float tt = (threadIdx.x < (int)(blockDim.x / 32)) ? s_red[threadIdx.x] : 0.f;
#pragma unroll
        for (int o = 8; o; o >>= 1) tt += __shfl_down_sync(0xffffffffu, tt, o);
        if (threadIdx.x == 0)
            out[(size_t)N * DDIM] = 1.25f * tt / ((float)N * (float)DDIM);
    }
}

// ---------------------------------------------------------------------------
extern "C" void kernel_launch(void* const* d_in, const int* in_sizes, int n_in,
                              void* d_out, int out_size) {
    const float* x   = (const float*)d_in[0];   // [B,T,D] fp32
    const float* emb = (const float*)d_in[1];   // [K,D]  fp32
    float* out = (float*)d_out;                 // [N*D quant | 1 loss | N idx]
    const int N  = in_sizes[0] / DDIM;          // 131072
    const int nb = N / BLOCK;                   // 512

    cudaFuncSetAttribute(vq_main, cudaFuncAttributeMaxDynamicSharedMemorySize, SMEM_SZ);

    prep_esq<<<(KCODES + 255) / 256, 256>>>(emb);
    prep_frag<<<64, 256>>>(emb);
    vq_main<<<nb, BLOCK, SMEM_SZ>>>(x, emb, out, N);
    loss_kernel<<<1, 512>>>(out, nb, N);
}

// round 11
// speedup vs baseline: 3.1514x; 1.2476x over previous
#include <cuda_runtime.h>
#include <cuda_fp16.h>
#include <cstdint>

#define DDIM    64
#define KCODES  1024
#define NCHUNK  8
#define CPC     128          // codes per chunk
#define NSUB    4            // n32 subtiles per chunk
#define BLOCK   256          // 8 warps, 16 rows/warp -> 128 rows per block
#define RESCORE_TAU 2e-3f

// ---------------- device scratch (allocation-free rule) ----------------
__device__ float g_esq[KCODES];
// fp16 codebook fragments: [chunk][ks(4)][ntile(16)][lane(32)] -> {b0,b1}  (128 KB)
__device__ uint2 g_bfrag[NCHUNK][4][16][32];
__device__ float g_partials[1024];

// ---------------- helpers ----------------
__device__ __forceinline__ uint32_t packh(float lo, float hi) {
    __half2 h = __floats2half2_rn(lo, hi);
    return *reinterpret_cast<uint32_t*>(&h);
}
// split pair into fp16 hi + fp16 residual
__device__ __forceinline__ void split2h(float a, float b, uint32_t& h, uint32_t& m) {
    __half ha = __float2half_rn(a), hb = __float2half_rn(b);
    h = packh(__half2float(ha), __half2float(hb));
    m = packh(a - __half2float(ha), b - __half2float(hb));
}
#define MMA16816(D, A, b0v, b1v)                                             \
    asm volatile("mma.sync.aligned.m16n8k16.row.col.f32.f16.f16.f32 "        \
                 "{%0,%1,%2,%3}, {%4,%5,%6,%7}, {%8,%9}, {%0,%1,%2,%3};"     \
                 : "+f"((D)[0]), "+f"((D)[1]), "+f"((D)[2]), "+f"((D)[3])    \
                 : "r"((A)[0]), "r"((A)[1]), "r"((A)[2]), "r"((A)[3]),       \
                   "r"(b0v), "r"(b1v))

#define CP_ASYNC16(saddr, gptr) \
    asm volatile("cp.async.cg.shared.global [%0], [%1], 16;" :: "r"(saddr), "l"(gptr) : "memory")
#define CP_COMMIT() asm volatile("cp.async.commit_group;" ::: "memory")
#define CP_WAIT0()  asm volatile("cp.async.wait_group 0;" ::: "memory")

__device__ __forceinline__ uint32_t smem_u32(const void* p) {
    uint32_t a;
    asm("{ .reg .u64 t; cvta.to.shared.u64 t, %1; cvt.u32.u64 %0, t; }" : "=r"(a) : "l"(p));
    return a;
}
// reference-coarse distance: fl32(fl32(xsq+esq) - fl32(2*dot))
__device__ __forceinline__ float coarse_dist(float xsq, float esq, float dotf) {
    float t = __fadd_rn(xsq, esq);
    return __fadd_rn(t, -__fmul_rn(2.0f, dotf));
}
// embed 10-bit GLOBAL code into low mantissa bits
__device__ __forceinline__ float keyed(float d, uint32_t code) {
    return __uint_as_float((__float_as_uint(d) & 0xFFFFFC00u) | code);
}

// ---------------- prep (merged): |e|^2 + fp16 B fragments ----------------
// NEEDS >= 16384 threads: one thread per g_bfrag entry.
__global__ void prep(const float* __restrict__ emb) {
    int idx = blockIdx.x * blockDim.x + threadIdx.x;   // 16384 threads
    {
        int lane = idx & 31;
        int ntg  = (idx >> 5) & 15;
        int ks   = (idx >> 9) & 3;
        int c    = idx >> 11;
        if (c < NCHUNK) {
            int g = lane >> 2, t = lane & 3;
            int n = c * CPC + ntg * 8 + g;
            const float* e = emb + (size_t)n * DDIM + ks * 16;
            g_bfrag[c][ks][ntg][lane] =
                make_uint2(packh(e[2 * t], e[2 * t + 1]),
                           packh(e[2 * t + 8], e[2 * t + 9]));
        }
    }
    if (idx < KCODES) {
        const float4* e = (const float4*)(emb + (size_t)idx * DDIM);
        float s = 0.f;
#pragma unroll
        for (int i = 0; i < 16; i++) {
            float4 v = e[i];
            s += v.x * v.x + v.y * v.y + v.z * v.z + v.w * v.w;
        }
        g_esq[idx] = s;
    }
}

// ---------------- main kernel: 16 rows/warp, 2-pass fp16, keyed top-3 ----------------
__global__ __launch_bounds__(BLOCK, 2) void vq_main(
    const float* __restrict__ x, const float* __restrict__ emb,
    float* __restrict__ out, int N)
{
    __shared__ uint2 s_bfrag[2][4][16][32];   // 2 x 16 KB double buffer
    __shared__ float s_esq[KCODES];           // 4 KB
    __shared__ float s_red[BLOCK / 32];
    const uint32_t sb_frag = smem_u32(&s_bfrag[0][0][0][0]);

    const int tid = threadIdx.x, wid = tid >> 5, lane = tid & 31;
    const int g = lane >> 2, t = lane & 3;
    const int base = blockIdx.x * 128 + wid * 16;   // 16 rows per warp

    // ---- A fragments: xh + xm fp16 (single m16 tile) ----
    uint32_t Ah[4][4], Am[4][4];
    {
        const float* r0 = x + (size_t)(base + g) * DDIM;
        const float* r8 = r0 + 8 * DDIM;
#pragma unroll
        for (int ks = 0; ks < 4; ks++) {
            const float2* p0 = (const float2*)(r0 + ks * 16);
            const float2* p8 = (const float2*)(r8 + ks * 16);
            float2 v0a = p0[t], v0b = p0[t + 4];
            float2 v8a = p8[t], v8b = p8[t + 4];
            split2h(v0a.x, v0a.y, Ah[ks][0], Am[ks][0]);
            split2h(v8a.x, v8a.y, Ah[ks][1], Am[ks][1]);
            split2h(v0b.x, v0b.y, Ah[ks][2], Am[ks][2]);
            split2h(v8b.x, v8b.y, Ah[ks][3], Am[ks][3]);
        }
    }

    // ---- esq into smem + prefetch chunk 0 (16 KB) ----
    {
        const char* src = (const char*)&g_bfrag[0][0][0][0];
#pragma unroll
        for (int i = 0; i < 4; i++)
            CP_ASYNC16(sb_frag + tid * 16 + i * 4096, src + tid * 16 + i * 4096);
        CP_COMMIT();
        for (int i = tid; i < KCODES; i += BLOCK) s_esq[i] = g_esq[i];
    }
    CP_WAIT0();
    __syncthreads();

    // keyed top-3 per row (j=0: row g, j=1: row g+8), 10-bit global code key
    float fc1[2] = {3.4e38f, 3.4e38f};
    float fc2[2] = {3.4e38f, 3.4e38f};
    float fc3[2] = {3.4e38f, 3.4e38f};

#define TOP3_INS(j, dist, code) do {                                \
        float _f = keyed(dist, code);                               \
        float _t0 = fmaxf(fc1[j], _f); fc1[j] = fminf(fc1[j], _f);  \
        float _t1 = fmaxf(fc2[j], _t0); fc2[j] = fminf(fc2[j], _t0);\
        fc3[j] = fminf(fc3[j], _t1);                                \
    } while (0)

    for (int c = 0; c < NCHUNK; c++) {
        const int cur = c & 1;
        if (c < NCHUNK - 1) {   // prefetch next chunk into other buffer
            const char* src = (const char*)&g_bfrag[c + 1][0][0][0];
            const uint32_t dst = sb_frag + (cur ^ 1) * 16384;
#pragma unroll
            for (int i = 0; i < 4; i++)
                CP_ASYNC16(dst + tid * 16 + i * 4096, src + tid * 16 + i * 4096);
            CP_COMMIT();
        }
        const uint2* bf = &s_bfrag[cur][0][0][0];

        for (int sub = 0; sub < NSUB; sub++) {
            float acc[4][4];
#pragma unroll
            for (int nt = 0; nt < 4; nt++)
#pragma unroll
                for (int q = 0; q < 4; q++) acc[nt][q] = 0.f;

            // 2 passes sharing the same B (eh): xh*eh + xm*eh = x*eh
#pragma unroll
            for (int ks = 0; ks < 4; ks++) {
                uint2 b[4];
#pragma unroll
                for (int nt = 0; nt < 4; nt++)
                    b[nt] = bf[(ks * 16 + sub * 4 + nt) * 32 + lane];
#pragma unroll
                for (int nt = 0; nt < 4; nt++)
                    MMA16816(acc[nt], Ah[ks], b[nt].x, b[nt].y);
#pragma unroll
                for (int nt = 0; nt < 4; nt++)
                    MMA16816(acc[nt], Am[ks], b[nt].x, b[nt].y);
            }

            // epilogue: dist = esq - 2*dot, keyed top-3
#pragma unroll
            for (int nt = 0; nt < 4; nt++) {
                const int ntg = sub * 4 + nt;
                float2 es = *(const float2*)&s_esq[c * CPC + ntg * 8 + 2 * t];
                const uint32_t k0 = (uint32_t)(c * CPC + ntg * 8 + 2 * t);
                TOP3_INS(0, fmaf(-2.f, acc[nt][0], es.x), k0);
                TOP3_INS(0, fmaf(-2.f, acc[nt][1], es.y), k0 + 1);
                TOP3_INS(1, fmaf(-2.f, acc[nt][2], es.x), k0);
                TOP3_INS(1, fmaf(-2.f, acc[nt][3], es.y), k0 + 1);
            }
        }

        if (c < NCHUNK - 1) CP_WAIT0();
        __syncthreads();
    }

    // ---- merge sorted top-3 across the 4-lane t-group (keyed values are distinct) ----
#pragma unroll
    for (int off = 1; off <= 2; off <<= 1) {
#pragma unroll
        for (int j = 0; j < 2; j++) {
            float o1 = __shfl_xor_sync(0xffffffffu, fc1[j], off);
            float o2 = __shfl_xor_sync(0xffffffffu, fc2[j], off);
            float o3 = __shfl_xor_sync(0xffffffffu, fc3[j], off);
            float hi1 = fmaxf(fc1[j], o1), c1 = fminf(fc1[j], o1);
            float lo2 = fminf(fc2[j], o2), hi2 = fmaxf(fc2[j], o2);
            float lo3 = fminf(fc3[j], o3);
            float c2 = fminf(hi1, lo2);
            float c3 = fminf(fmaxf(hi1, lo2), fminf(hi2, lo3));
            fc1[j] = c1; fc2[j] = c2; fc3[j] = c3;
        }
    }

    // ---- decode + near-tie rescore with the REFERENCE's coarse fp32 arithmetic ----
    int gi[2];
#pragma unroll
    for (int j = 0; j < 2; j++) {
        uint32_t b1 = __float_as_uint(fc1[j]);
        uint32_t b2 = __float_as_uint(fc2[j]);
        uint32_t b3 = __float_as_uint(fc3[j]);
        int   i1 = (int)(b1 & 1023u), i2 = (int)(b2 & 1023u), i3 = (int)(b3 & 1023u);
        float f1 = __uint_as_float(b1 & 0xFFFFFC00u);
        float f2 = __uint_as_float(b2 & 0xFFFFFC00u);
        float f3 = __uint_as_float(b3 & 0xFFFFFC00u);
        gi[j] = i1;
        if (f2 - f1 < RESCORE_TAU) {
            const int row = base + j * 8 + g;
            const float* xr = x + (size_t)row * DDIM;
            float xsq = 0.f;
            for (int k = 0; k < DDIM; k++)
                xsq = __fadd_rn(xsq, __fmul_rn(xr[k], xr[k]));
            const bool use3 = (f3 - f1 < RESCORE_TAU);
            const float* e1 = emb + (size_t)i1 * DDIM;
            const float* e2 = emb + (size_t)i2 * DDIM;
            const float* e3 = emb + (size_t)i3 * DDIM;
            double d1 = 0.0, d2 = 0.0, d3 = 0.0;
            for (int k = 0; k < DDIM; k++) {
                double xv = (double)xr[k];
                d1 = fma(xv, (double)e1[k], d1);
                d2 = fma(xv, (double)e2[k], d2);
                if (use3) d3 = fma(xv, (double)e3[k], d3);
            }
            float c1d = coarse_dist(xsq, g_esq[i1], (float)d1);
            float c2d = coarse_dist(xsq, g_esq[i2], (float)d2);
            int   bi = i1; float bd = c1d;
            if (c2d < bd || (c2d == bd && i2 < bi)) { bd = c2d; bi = i2; }
            if (use3) {
                float c3d = coarse_dist(xsq, g_esq[i3], (float)d3);
                if (c3d < bd || (c3d == bd && i3 < bi)) { bd = c3d; bi = i3; }
            }
            gi[j] = bi;
        }
    }

    // ---- outputs: quant gather (exact fp32), indices, exact loss partial ----
    float errsum = 0.f;
#pragma unroll
    for (int j = 0; j < 2; j++) {
        const int row = base + j * 8 + g;
        const int idx = gi[j];
        if (t == 0) out[(size_t)N * DDIM + 1 + row] = (float)idx;
        const float4* ep = (const float4*)(emb + (size_t)idx * DDIM + t * 16);
        const float4* xp = (const float4*)(x + (size_t)row * DDIM + t * 16);
        float4* op = (float4*)(out + (size_t)row * DDIM + t * 16);
#pragma unroll
        for (int q = 0; q < 4; q++) {
            float4 e = ep[q], v = xp[q];
            op[q] = e;
            float d0 = e.x - v.x, d1 = e.y - v.y, d2 = e.z - v.z, d3 = e.w - v.w;
            errsum += d0 * d0 + d1 * d1 + d2 * d2 + d3 * d3;
        }
    }
#pragma unroll
    for (int o = 16; o; o >>= 1) errsum += __shfl_down_sync(0xffffffffu, errsum, o);
    if (lane == 0) s_red[wid] = errsum;
    __syncthreads();
    if (tid == 0) {
        float s = 0.f;
#pragma unroll
        for (int w = 0; w < BLOCK / 32; w++) s += s_red[w];
        g_partials[blockIdx.x] = s;
    }
}

// ---------------- final loss reduction (1024 threads = 32 warps!) ----------------
__global__ void loss_kernel(float* __restrict__ out, int nblocks, int N) {
    __shared__ float s_red[32];          // FIXED: was [16] with 32 warps -> OOB smem
    float v = 0.f;
    for (int i = threadIdx.x; i < nblocks; i += blockDim.x) v += g_partials[i];
#pragma unroll
    for (int o = 16; o; o >>= 1) v += __shfl_down_sync(0xffffffffu, v, o);
    if ((threadIdx.x & 31) == 0) s_red[threadIdx.x >> 5] = v;
    __syncthreads();
    if (threadIdx.x < 32) {
        float tt = (threadIdx.x < (int)(blockDim.x >> 5)) ? s_red[threadIdx.x] : 0.f;
#pragma unroll
        for (int o = 16; o; o >>= 1) tt += __shfl_down_sync(0xffffffffu, tt, o);
        if (threadIdx.x == 0)
            out[(size_t)N * DDIM] = 1.25f * tt / ((float)N * (float)DDIM);
    }
}

// dummy: aligns the launch period so ncu (-s 5 -c 1) captures vq_main
__global__ void align_k() {}

// ---------------------------------------------------------------------------
extern "C" void kernel_launch(void* const* d_in, const int* in_sizes, int n_in,
                              void* d_out, int out_size) {
    const float* x   = (const float*)d_in[0];   // [B,T,D] fp32
    const float* emb = (const float*)d_in[1];   // [K,D]  fp32
    float* out = (float*)d_out;                 // [N*D quant | 1 loss | N idx]
    const int N  = in_sizes[0] / DDIM;          // 131072
    const int nb = N / 128;                     // 1024

    // period-4 launch sequence, vq_main at position 1 -> global launch idx 5 is vq_main
    prep<<<64, 256>>>(emb);
    vq_main<<<nb, BLOCK>>>(x, emb, out, N);
    loss_kernel<<<1, 1024>>>(out, nb, N);
    align_k<<<1, 32>>>();
}

// round 12
// speedup vs baseline: 4.0421x; 1.2827x over previous
#include <cuda_runtime.h>
#include <cuda_fp16.h>
#include <cstdint>

#define DDIM    64
#define KCODES  1024
#define NCHUNK  8
#define CPC     128          // codes per chunk
#define NSUB    4            // n32 subtiles per chunk
#define BLOCK   256          // 8 warps, 16 rows/warp -> 128 rows per block
#define RESCORE_TAU 2e-3f

// ---------------- device scratch (allocation-free rule) ----------------
__device__ float g_esq[KCODES];
// fp16 codebook fragments: [chunk][ks(4)][ntile(16)][lane(32)] -> {b0,b1}  (128 KB)
__device__ uint2 g_bfrag[NCHUNK][4][16][32];
__device__ float g_partials[1024];

// ---------------- helpers ----------------
__device__ __forceinline__ uint32_t packh(float lo, float hi) {
    __half2 h = __floats2half2_rn(lo, hi);
    return *reinterpret_cast<uint32_t*>(&h);
}
#define MMA16816(D, A, b0v, b1v)                                             \
    asm volatile("mma.sync.aligned.m16n8k16.row.col.f32.f16.f16.f32 "        \
                 "{%0,%1,%2,%3}, {%4,%5,%6,%7}, {%8,%9}, {%0,%1,%2,%3};"     \
                 : "+f"((D)[0]), "+f"((D)[1]), "+f"((D)[2]), "+f"((D)[3])    \
                 : "r"((A)[0]), "r"((A)[1]), "r"((A)[2]), "r"((A)[3]),       \
                   "r"(b0v), "r"(b1v))

#define CP_ASYNC16(saddr, gptr) \
    asm volatile("cp.async.cg.shared.global [%0], [%1], 16;" :: "r"(saddr), "l"(gptr) : "memory")
#define CP_COMMIT() asm volatile("cp.async.commit_group;" ::: "memory")
#define CP_WAIT0()  asm volatile("cp.async.wait_group 0;" ::: "memory")

__device__ __forceinline__ uint32_t smem_u32(const void* p) {
    uint32_t a;
    asm("{ .reg .u64 t; cvta.to.shared.u64 t, %1; cvt.u32.u64 %0, t; }" : "=r"(a) : "l"(p));
    return a;
}
// reference-coarse distance: fl32(fl32(xsq+esq) - fl32(2*dot))
__device__ __forceinline__ float coarse_dist(float xsq, float esq, float dotf) {
    float t = __fadd_rn(xsq, esq);
    return __fadd_rn(t, -__fmul_rn(2.0f, dotf));
}
// embed 10-bit GLOBAL code into low mantissa bits
__device__ __forceinline__ float keyed(float d, uint32_t code) {
    return __uint_as_float((__float_as_uint(d) & 0xFFFFFC00u) | code);
}

// ---------------- prep (merged): |e|^2 + fp16 B fragments ----------------
// NEEDS >= 16384 threads: one thread per g_bfrag entry.
__global__ void prep(const float* __restrict__ emb) {
    int idx = blockIdx.x * blockDim.x + threadIdx.x;   // 16384 threads
    {
        int lane = idx & 31;
        int ntg  = (idx >> 5) & 15;
        int ks   = (idx >> 9) & 3;
        int c    = idx >> 11;
        if (c < NCHUNK) {
            int g = lane >> 2, t = lane & 3;
            int n = c * CPC + ntg * 8 + g;
            const float* e = emb + (size_t)n * DDIM + ks * 16;
            g_bfrag[c][ks][ntg][lane] =
                make_uint2(packh(e[2 * t], e[2 * t + 1]),
                           packh(e[2 * t + 8], e[2 * t + 9]));
        }
    }
    if (idx < KCODES) {
        const float4* e = (const float4*)(emb + (size_t)idx * DDIM);
        float s = 0.f;
#pragma unroll
        for (int i = 0; i < 16; i++) {
            float4 v = e[i];
            s += v.x * v.x + v.y * v.y + v.z * v.z + v.w * v.w;
        }
        g_esq[idx] = s;
    }
}

// ---------------- main kernel: 16 rows/warp, 1-pass fp16, keyed top-3 ----------------
__global__ __launch_bounds__(BLOCK, 3) void vq_main(
    const float* __restrict__ x, const float* __restrict__ emb,
    float* __restrict__ out, int N)
{
    __shared__ uint2 s_bfrag[2][4][16][32];   // 2 x 16 KB double buffer
    __shared__ float s_esq[KCODES];           // 4 KB
    __shared__ float s_red[BLOCK / 32];
    const uint32_t sb_frag = smem_u32(&s_bfrag[0][0][0][0]);

    const int tid = threadIdx.x, wid = tid >> 5, lane = tid & 31;
    const int g = lane >> 2, t = lane & 3;
    const int base = blockIdx.x * 128 + wid * 16;   // 16 rows per warp

    // ---- A fragments: plain fp16 (1-pass; rescore machinery absorbs the error) ----
    uint32_t Ah[4][4];
    {
        const float* r0 = x + (size_t)(base + g) * DDIM;
        const float* r8 = r0 + 8 * DDIM;
#pragma unroll
        for (int ks = 0; ks < 4; ks++) {
            const float2* p0 = (const float2*)(r0 + ks * 16);
            const float2* p8 = (const float2*)(r8 + ks * 16);
            float2 v0a = p0[t], v0b = p0[t + 4];
            float2 v8a = p8[t], v8b = p8[t + 4];
            Ah[ks][0] = packh(v0a.x, v0a.y);
            Ah[ks][1] = packh(v8a.x, v8a.y);
            Ah[ks][2] = packh(v0b.x, v0b.y);
            Ah[ks][3] = packh(v8b.x, v8b.y);
        }
    }

    // ---- esq into smem + prefetch chunk 0 (16 KB) ----
    {
        const char* src = (const char*)&g_bfrag[0][0][0][0];
#pragma unroll
        for (int i = 0; i < 4; i++)
            CP_ASYNC16(sb_frag + tid * 16 + i * 4096, src + tid * 16 + i * 4096);
        CP_COMMIT();
        for (int i = tid; i < KCODES; i += BLOCK) s_esq[i] = g_esq[i];
    }
    CP_WAIT0();
    __syncthreads();

    // keyed top-3 per row (j=0: row g, j=1: row g+8), 10-bit global code key
    float fc1[2] = {3.4e38f, 3.4e38f};
    float fc2[2] = {3.4e38f, 3.4e38f};
    float fc3[2] = {3.4e38f, 3.4e38f};

#define TOP3_INS(j, dist, code) do {                                \
        float _f = keyed(dist, code);                               \
        float _t0 = fmaxf(fc1[j], _f); fc1[j] = fminf(fc1[j], _f);  \
        float _t1 = fmaxf(fc2[j], _t0); fc2[j] = fminf(fc2[j], _t0);\
        fc3[j] = fminf(fc3[j], _t1);                                \
    } while (0)

    for (int c = 0; c < NCHUNK; c++) {
        const int cur = c & 1;
        if (c < NCHUNK - 1) {   // prefetch next chunk into other buffer
            const char* src = (const char*)&g_bfrag[c + 1][0][0][0];
            const uint32_t dst = sb_frag + (cur ^ 1) * 16384;
#pragma unroll
            for (int i = 0; i < 4; i++)
                CP_ASYNC16(dst + tid * 16 + i * 4096, src + tid * 16 + i * 4096);
            CP_COMMIT();
        }
        const uint2* bf = &s_bfrag[cur][0][0][0];

        for (int sub = 0; sub < NSUB; sub++) {
            float acc[4][4];
#pragma unroll
            for (int nt = 0; nt < 4; nt++)
#pragma unroll
                for (int q = 0; q < 4; q++) acc[nt][q] = 0.f;

            // single fp16 pass: dot = fl16(x) . fl16(e), fp32 accumulate
#pragma unroll
            for (int ks = 0; ks < 4; ks++) {
                uint2 b[4];
#pragma unroll
                for (int nt = 0; nt < 4; nt++)
                    b[nt] = bf[(ks * 16 + sub * 4 + nt) * 32 + lane];
#pragma unroll
                for (int nt = 0; nt < 4; nt++)
                    MMA16816(acc[nt], Ah[ks], b[nt].x, b[nt].y);
            }

            // epilogue: dist = esq - 2*dot, keyed top-3
#pragma unroll
            for (int nt = 0; nt < 4; nt++) {
                const int ntg = sub * 4 + nt;
                float2 es = *(const float2*)&s_esq[c * CPC + ntg * 8 + 2 * t];
                const uint32_t k0 = (uint32_t)(c * CPC + ntg * 8 + 2 * t);
                TOP3_INS(0, fmaf(-2.f, acc[nt][0], es.x), k0);
                TOP3_INS(0, fmaf(-2.f, acc[nt][1], es.y), k0 + 1);
                TOP3_INS(1, fmaf(-2.f, acc[nt][2], es.x), k0);
                TOP3_INS(1, fmaf(-2.f, acc[nt][3], es.y), k0 + 1);
            }
        }

        if (c < NCHUNK - 1) CP_WAIT0();
        __syncthreads();
    }

    // ---- merge sorted top-3 across the 4-lane t-group (keyed values are distinct) ----
#pragma unroll
    for (int off = 1; off <= 2; off <<= 1) {
#pragma unroll
        for (int j = 0; j < 2; j++) {
            float o1 = __shfl_xor_sync(0xffffffffu, fc1[j], off);
            float o2 = __shfl_xor_sync(0xffffffffu, fc2[j], off);
            float o3 = __shfl_xor_sync(0xffffffffu, fc3[j], off);
            float hi1 = fmaxf(fc1[j], o1), c1 = fminf(fc1[j], o1);
            float lo2 = fminf(fc2[j], o2), hi2 = fmaxf(fc2[j], o2);
            float lo3 = fminf(fc3[j], o3);
            float c2 = fminf(hi1, lo2);
            float c3 = fminf(fmaxf(hi1, lo2), fminf(hi2, lo3));
            fc1[j] = c1; fc2[j] = c2; fc3[j] = c3;
        }
    }

    // ---- decode + near-tie rescore with the REFERENCE's coarse fp32 arithmetic ----
    int gi[2];
#pragma unroll
    for (int j = 0; j < 2; j++) {
        uint32_t b1 = __float_as_uint(fc1[j]);
        uint32_t b2 = __float_as_uint(fc2[j]);
        uint32_t b3 = __float_as_uint(fc3[j]);
        int   i1 = (int)(b1 & 1023u), i2 = (int)(b2 & 1023u), i3 = (int)(b3 & 1023u);
        float f1 = __uint_as_float(b1 & 0xFFFFFC00u);
        float f2 = __uint_as_float(b2 & 0xFFFFFC00u);
        float f3 = __uint_as_float(b3 & 0xFFFFFC00u);
        gi[j] = i1;
        if (f2 - f1 < RESCORE_TAU) {
            const int row = base + j * 8 + g;
            const float* xr = x + (size_t)row * DDIM;
            float xsq = 0.f;
            for (int k = 0; k < DDIM; k++)
                xsq = __fadd_rn(xsq, __fmul_rn(xr[k], xr[k]));
            const bool use3 = (f3 - f1 < RESCORE_TAU);
            const float* e1 = emb + (size_t)i1 * DDIM;
            const float* e2 = emb + (size_t)i2 * DDIM;
            const float* e3 = emb + (size_t)i3 * DDIM;
            double d1 = 0.0, d2 = 0.0, d3 = 0.0;
            for (int k = 0; k < DDIM; k++) {
                double xv = (double)xr[k];
                d1 = fma(xv, (double)e1[k], d1);
                d2 = fma(xv, (double)e2[k], d2);
                if (use3) d3 = fma(xv, (double)e3[k], d3);
            }
            float c1d = coarse_dist(xsq, g_esq[i1], (float)d1);
            float c2d = coarse_dist(xsq, g_esq[i2], (float)d2);
            int   bi = i1; float bd = c1d;
            if (c2d < bd || (c2d == bd && i2 < bi)) { bd = c2d; bi = i2; }
            if (use3) {
                float c3d = coarse_dist(xsq, g_esq[i3], (float)d3);
                if (c3d < bd || (c3d == bd && i3 < bi)) { bd = c3d; bi = i3; }
            }
            gi[j] = bi;
        }
    }

    // ---- outputs: quant gather (exact fp32), indices, exact loss partial ----
    float errsum = 0.f;
#pragma unroll
    for (int j = 0; j < 2; j++) {
        const int row = base + j * 8 + g;
        const int idx = gi[j];
        if (t == 0) out[(size_t)N * DDIM + 1 + row] = (float)idx;
        const float4* ep = (const float4*)(emb + (size_t)idx * DDIM + t * 16);
        const float4* xp = (const float4*)(x + (size_t)row * DDIM + t * 16);
        float4* op = (float4*)(out + (size_t)row * DDIM + t * 16);
#pragma unroll
        for (int q = 0; q < 4; q++) {
            float4 e = ep[q], v = xp[q];
            op[q] = e;
            float d0 = e.x - v.x, d1 = e.y - v.y, d2 = e.z - v.z, d3 = e.w - v.w;
            errsum += d0 * d0 + d1 * d1 + d2 * d2 + d3 * d3;
        }
    }
#pragma unroll
    for (int o = 16; o; o >>= 1) errsum += __shfl_down_sync(0xffffffffu, errsum, o);
    if (lane == 0) s_red[wid] = errsum;
    __syncthreads();
    if (tid == 0) {
        float s = 0.f;
#pragma unroll
        for (int w = 0; w < BLOCK / 32; w++) s += s_red[w];
        g_partials[blockIdx.x] = s;
    }
}

// ---------------- final loss reduction (1024 threads = 32 warps) ----------------
__global__ void loss_kernel(float* __restrict__ out, int nblocks, int N) {
    __shared__ float s_red[32];
    float v = 0.f;
    for (int i = threadIdx.x; i < nblocks; i += blockDim.x) v += g_partials[i];
#pragma unroll
    for (int o = 16; o; o >>= 1) v += __shfl_down_sync(0xffffffffu, v, o);
    if ((threadIdx.x & 31) == 0) s_red[threadIdx.x >> 5] = v;
    __syncthreads();
    if (threadIdx.x < 32) {
        float tt = (threadIdx.x < (int)(blockDim.x >> 5)) ? s_red[threadIdx.x] : 0.f;
#pragma unroll
        for (int o = 16; o; o >>= 1) tt += __shfl_down_sync(0xffffffffu, tt, o);
        if (threadIdx.x == 0)
            out[(size_t)N * DDIM] = 1.25f * tt / ((float)N * (float)DDIM);
    }
}

// ---------------------------------------------------------------------------
extern "C" void kernel_launch(void* const* d_in, const int* in_sizes, int n_in,
                              void* d_out, int out_size) {
    const float* x   = (const float*)d_in[0];   // [B,T,D] fp32
    const float* emb = (const float*)d_in[1];   // [K,D]  fp32
    float* out = (float*)d_out;                 // [N*D quant | 1 loss | N idx]
    const int N  = in_sizes[0] / DDIM;          // 131072
    const int nb = N / 128;                     // 1024

    prep<<<64, 256>>>(emb);
    vq_main<<<nb, BLOCK>>>(x, emb, out, N);
    loss_kernel<<<1, 1024>>>(out, nb, N);
}